// round 1
// baseline (speedup 1.0000x reference)
#include <cuda_runtime.h>

#define BATCH 2
#define SEQ   2048
#define HID   768
#define NHEAD 12
#define HDIM  64
#define MTOK  (BATCH*SEQ)          // 4096
#define GAMMA 0.05f
#define LNEPS 1e-12f

// ---------------- scratch (no allocations allowed) ----------------
__device__ float g_q[MTOK*HID];
__device__ float g_k[MTOK*HID];
__device__ float g_v[MTOK*HID];
__device__ float g_ctx[MTOK*HID];
__device__ float g_y[MTOK*HID];

// ---------------- generic projection GEMM: C = A @ W^T + bias (+res) ----------------
// A: [MTOK, HID], W: [HID, HID] row-major (row = out feature), C: [MTOK, HID]
// gamma_mode: apply w -> w + GAMMA*max(w,0) (and same to bias), add residual.
__global__ __launch_bounds__(256)
void proj_gemm(const float* __restrict__ A, const float* __restrict__ W,
               const float* __restrict__ bias, const float* __restrict__ res,
               float* __restrict__ C, int gamma_mode)
{
    __shared__ float As[32][65];
    __shared__ float Ws[32][65];
    const int tid = threadIdx.x;
    const int tx = tid & 15, ty = tid >> 4;
    const int bm = blockIdx.x * 64;
    const int bn = blockIdx.y * 64;
    float acc[4][4] = {};

    for (int k0 = 0; k0 < HID; k0 += 32) {
        #pragma unroll
        for (int i = 0; i < 8; i++) {
            int idx = tid + i * 256;
            int m = idx >> 5, k = idx & 31;
            As[k][m] = A[(size_t)(bm + m) * HID + k0 + k];
        }
        #pragma unroll
        for (int i = 0; i < 8; i++) {
            int idx = tid + i * 256;
            int n = idx >> 5, k = idx & 31;
            float w = W[(size_t)(bn + n) * HID + k0 + k];
            if (gamma_mode) w += GAMMA * fmaxf(w, 0.f);
            Ws[k][n] = w;
        }
        __syncthreads();
        #pragma unroll
        for (int k = 0; k < 32; k++) {
            float a[4], w[4];
            #pragma unroll
            for (int i = 0; i < 4; i++) a[i] = As[k][ty * 4 + i];
            #pragma unroll
            for (int j = 0; j < 4; j++) w[j] = Ws[k][tx * 4 + j];
            #pragma unroll
            for (int i = 0; i < 4; i++)
                #pragma unroll
                for (int j = 0; j < 4; j++)
                    acc[i][j] += a[i] * w[j];
        }
        __syncthreads();
    }

    #pragma unroll
    for (int i = 0; i < 4; i++) {
        int m = bm + ty * 4 + i;
        #pragma unroll
        for (int j = 0; j < 4; j++) {
            int n = bn + tx * 4 + j;
            float b = bias[n];
            if (gamma_mode) b += GAMMA * fmaxf(b, 0.f);
            float v = acc[i][j] + b;
            if (res) v += res[(size_t)m * HID + n];
            C[(size_t)m * HID + n] = v;
        }
    }
}

// ---------------- scores = Q @ K^T per (b,h); writes raw scores into probs region ----------------
__global__ __launch_bounds__(256)
void scores_kernel(float* __restrict__ probs)
{
    __shared__ float Qs[32][129];
    __shared__ float Ks[32][129];
    const int bh = blockIdx.z;                // 0..23
    const int b = bh / NHEAD, h = bh % NHEAD;
    const int s0 = blockIdx.x * 128;
    const int t0 = blockIdx.y * 128;
    const float* qbase = g_q + (size_t)b * SEQ * HID + h * HDIM;
    const float* kbase = g_k + (size_t)b * SEQ * HID + h * HDIM;
    const int tid = threadIdx.x;
    const int tx = tid & 15, ty = tid >> 4;
    float acc[8][8] = {};

    #pragma unroll
    for (int k0 = 0; k0 < HDIM; k0 += 32) {
        #pragma unroll
        for (int i = 0; i < 16; i++) {
            int idx = tid + i * 256;
            int m = idx >> 5, k = idx & 31;
            Qs[k][m] = qbase[(size_t)(s0 + m) * HID + k0 + k];
            Ks[k][m] = kbase[(size_t)(t0 + m) * HID + k0 + k];
        }
        __syncthreads();
        #pragma unroll
        for (int k = 0; k < 32; k++) {
            float a[8], bb[8];
            #pragma unroll
            for (int i = 0; i < 8; i++) a[i] = Qs[k][ty * 8 + i];
            #pragma unroll
            for (int j = 0; j < 8; j++) bb[j] = Ks[k][tx * 8 + j];
            #pragma unroll
            for (int i = 0; i < 8; i++)
                #pragma unroll
                for (int j = 0; j < 8; j++)
                    acc[i][j] += a[i] * bb[j];
        }
        __syncthreads();
    }

    float* out = probs + ((size_t)bh * SEQ + s0) * SEQ + t0;
    #pragma unroll
    for (int i = 0; i < 8; i++)
        #pragma unroll
        for (int j = 0; j < 8; j++)
            out[(size_t)(ty * 8 + i) * SEQ + tx * 8 + j] = acc[i][j];
}

// ---------------- in-place row softmax over 2048 cols ----------------
__global__ __launch_bounds__(256)
void softmax_kernel(float* __restrict__ probs)
{
    float* p = probs + (size_t)blockIdx.x * SEQ;
    const int tid = threadIdx.x;
    __shared__ float sh[8];

    float vals[8];
    float mx = -1e30f;
    #pragma unroll
    for (int i = 0; i < 8; i++) {
        vals[i] = p[tid + i * 256];
        mx = fmaxf(mx, vals[i]);
    }
    #pragma unroll
    for (int o = 16; o; o >>= 1) mx = fmaxf(mx, __shfl_xor_sync(0xffffffffu, mx, o));
    if ((tid & 31) == 0) sh[tid >> 5] = mx;
    __syncthreads();
    mx = sh[0];
    #pragma unroll
    for (int i = 1; i < 8; i++) mx = fmaxf(mx, sh[i]);
    __syncthreads();

    float sum = 0.f;
    #pragma unroll
    for (int i = 0; i < 8; i++) {
        vals[i] = __expf(vals[i] - mx);
        sum += vals[i];
    }
    #pragma unroll
    for (int o = 16; o; o >>= 1) sum += __shfl_xor_sync(0xffffffffu, sum, o);
    if ((tid & 31) == 0) sh[tid >> 5] = sum;
    __syncthreads();
    sum = 0.f;
    #pragma unroll
    for (int i = 0; i < 8; i++) sum += sh[i];
    float inv = 1.f / sum;
    #pragma unroll
    for (int i = 0; i < 8; i++) p[tid + i * 256] = vals[i] * inv;
}

// ---------------- ctx = P @ V per (b,h); writes into [tok, h*64+d] layout ----------------
__global__ __launch_bounds__(256)
void pv_kernel(const float* __restrict__ probs)
{
    __shared__ float Ps[32][129];   // [t][s]
    __shared__ float Vs[32][65];    // [t][d]
    const int bh = blockIdx.y;
    const int b = bh / NHEAD, h = bh % NHEAD;
    const int s0 = blockIdx.x * 128;
    const float* pbase = probs + ((size_t)bh * SEQ + s0) * SEQ;
    const float* vbase = g_v + (size_t)b * SEQ * HID + h * HDIM;
    float* cbase = g_ctx + (size_t)(b * SEQ + s0) * HID + h * HDIM;
    const int tid = threadIdx.x;
    const int tx = tid & 15, ty = tid >> 4;
    float acc[8][4] = {};

    for (int t0 = 0; t0 < SEQ; t0 += 32) {
        #pragma unroll
        for (int i = 0; i < 16; i++) {
            int idx = tid + i * 256;
            int m = idx >> 5, t = idx & 31;
            Ps[t][m] = pbase[(size_t)m * SEQ + t0 + t];
        }
        #pragma unroll
        for (int i = 0; i < 8; i++) {
            int idx = tid + i * 256;
            int t = idx >> 6, d = idx & 63;
            Vs[t][d] = vbase[(size_t)(t0 + t) * HID + d];
        }
        __syncthreads();
        #pragma unroll
        for (int t = 0; t < 32; t++) {
            float a[8], vv[4];
            #pragma unroll
            for (int i = 0; i < 8; i++) a[i] = Ps[t][ty * 8 + i];
            #pragma unroll
            for (int j = 0; j < 4; j++) vv[j] = Vs[t][tx * 4 + j];
            #pragma unroll
            for (int i = 0; i < 8; i++)
                #pragma unroll
                for (int j = 0; j < 4; j++)
                    acc[i][j] += a[i] * vv[j];
        }
        __syncthreads();
    }

    #pragma unroll
    for (int i = 0; i < 8; i++)
        #pragma unroll
        for (int j = 0; j < 4; j++)
            cbase[(size_t)(ty * 8 + i) * HID + tx * 4 + j] = acc[i][j];
}

// ---------------- 'nowb' LayerNorm: (y - mean) / (std_ddof1 + eps) ----------------
__global__ __launch_bounds__(256)
void ln_kernel(const float* __restrict__ y, float* __restrict__ out)
{
    const float* yr = y + (size_t)blockIdx.x * HID;
    float* orow = out + (size_t)blockIdx.x * HID;
    const int tid = threadIdx.x;
    __shared__ float sh[8];

    float v[3];
    float sum = 0.f;
    #pragma unroll
    for (int i = 0; i < 3; i++) { v[i] = yr[tid + i * 256]; sum += v[i]; }
    #pragma unroll
    for (int o = 16; o; o >>= 1) sum += __shfl_xor_sync(0xffffffffu, sum, o);
    if ((tid & 31) == 0) sh[tid >> 5] = sum;
    __syncthreads();
    sum = 0.f;
    #pragma unroll
    for (int i = 0; i < 8; i++) sum += sh[i];
    float mean = sum * (1.f / HID);
    __syncthreads();

    float ss = 0.f;
    #pragma unroll
    for (int i = 0; i < 3; i++) { float d = v[i] - mean; ss += d * d; }
    #pragma unroll
    for (int o = 16; o; o >>= 1) ss += __shfl_xor_sync(0xffffffffu, ss, o);
    if ((tid & 31) == 0) sh[tid >> 5] = ss;
    __syncthreads();
    ss = 0.f;
    #pragma unroll
    for (int i = 0; i < 8; i++) ss += sh[i];
    float stdv = sqrtf(ss * (1.f / (HID - 1)));   // ddof=1
    float inv = 1.f / (stdv + LNEPS);
    #pragma unroll
    for (int i = 0; i < 3; i++) orow[tid + i * 256] = (v[i] - mean) * inv;
}

// ---------------- launch ----------------
extern "C" void kernel_launch(void* const* d_in, const int* in_sizes, int n_in,
                              void* d_out, int out_size)
{
    const float* x  = (const float*)d_in[0];
    const float* Wq = (const float*)d_in[1];
    const float* bq = (const float*)d_in[2];
    const float* Wk = (const float*)d_in[3];
    const float* bk = (const float*)d_in[4];
    const float* Wv = (const float*)d_in[5];
    const float* bv = (const float*)d_in[6];
    const float* Wo = (const float*)d_in[7];
    const float* bo = (const float*)d_in[8];

    float* out   = (float*)d_out;                       // [B,S,H] = 3,145,728 floats
    float* probs = out + (size_t)MTOK * HID;            // [B,NH,S,S] = 100,663,296 floats

    float *q, *k, *v, *ctx, *y;
    cudaGetSymbolAddress((void**)&q,   g_q);
    cudaGetSymbolAddress((void**)&k,   g_k);
    cudaGetSymbolAddress((void**)&v,   g_v);
    cudaGetSymbolAddress((void**)&ctx, g_ctx);
    cudaGetSymbolAddress((void**)&y,   g_y);

    dim3 gproj(MTOK / 64, HID / 64);                    // (64, 12)
    proj_gemm<<<gproj, 256>>>(x, Wq, bq, nullptr, q, 0);
    proj_gemm<<<gproj, 256>>>(x, Wk, bk, nullptr, k, 0);
    proj_gemm<<<gproj, 256>>>(x, Wv, bv, nullptr, v, 0);

    scores_kernel<<<dim3(SEQ / 128, SEQ / 128, BATCH * NHEAD), 256>>>(probs);

    softmax_kernel<<<BATCH * NHEAD * SEQ, 256>>>(probs);

    pv_kernel<<<dim3(SEQ / 128, BATCH * NHEAD), 256>>>(probs);

    proj_gemm<<<gproj, 256>>>(ctx, Wo, bo, x, y, 1);    // gamma-modified + residual

    ln_kernel<<<MTOK, 256>>>(y, out);
}

// round 2
// speedup vs baseline: 1.3651x; 1.3651x over previous
#include <cuda_runtime.h>

#define BATCH 2
#define SEQ   2048
#define HID   768
#define NHEAD 12
#define HDIM  64
#define MTOK  (BATCH*SEQ)          // 4096
#define GAMMA 0.05f
#define LNEPS 1e-12f

// ---------------- scratch (no allocations allowed) ----------------
__device__ float g_q[MTOK*HID];
__device__ float g_k[MTOK*HID];
__device__ float g_v[MTOK*HID];
__device__ float g_ctx[MTOK*HID];
__device__ float g_y[MTOK*HID];

// ============ projection GEMM: C = A @ W^T + bias (+res), 128x64 tile ============
// A: [MTOK, HID], W: [HID, HID] row-major (row = out feature), C: [MTOK, HID]
__global__ __launch_bounds__(256, 2)
void proj_gemm(const float* __restrict__ A, const float* __restrict__ W,
               const float* __restrict__ bias, const float* __restrict__ res,
               float* __restrict__ C, int gamma_mode)
{
    __shared__ float As[32][132];   // [k][m]
    __shared__ float Ws[32][68];    // [k][n]
    const int tid = threadIdx.x;
    const int tx = tid & 15, ty = tid >> 4;
    const int bm = blockIdx.x * 128;
    const int bn = blockIdx.y * 64;
    float acc[8][4] = {};

    const float* Abase = A + (size_t)bm * HID;
    const float* Wbase = W + (size_t)bn * HID;

    for (int k0 = 0; k0 < HID; k0 += 32) {
        // A tile: 128 rows x 32 k  = 1024 float4 -> 4 per thread
        #pragma unroll
        for (int i = 0; i < 4; i++) {
            int f4 = tid + i * 256;
            int m = f4 >> 3, kk = (f4 & 7) * 4;
            float4 v = *(const float4*)(Abase + (size_t)m * HID + k0 + kk);
            As[kk + 0][m] = v.x; As[kk + 1][m] = v.y;
            As[kk + 2][m] = v.z; As[kk + 3][m] = v.w;
        }
        // W tile: 64 rows x 32 k = 512 float4 -> 2 per thread
        #pragma unroll
        for (int i = 0; i < 2; i++) {
            int f4 = tid + i * 256;
            int n = f4 >> 3, kk = (f4 & 7) * 4;
            float4 v = *(const float4*)(Wbase + (size_t)n * HID + k0 + kk);
            if (gamma_mode) {
                v.x += GAMMA * fmaxf(v.x, 0.f); v.y += GAMMA * fmaxf(v.y, 0.f);
                v.z += GAMMA * fmaxf(v.z, 0.f); v.w += GAMMA * fmaxf(v.w, 0.f);
            }
            Ws[kk + 0][n] = v.x; Ws[kk + 1][n] = v.y;
            Ws[kk + 2][n] = v.z; Ws[kk + 3][n] = v.w;
        }
        __syncthreads();
        #pragma unroll
        for (int k = 0; k < 32; k++) {
            float4 a0 = *(const float4*)&As[k][ty * 8];
            float4 a1 = *(const float4*)&As[k][ty * 8 + 4];
            float4 wv = *(const float4*)&Ws[k][tx * 4];
            float a[8] = {a0.x, a0.y, a0.z, a0.w, a1.x, a1.y, a1.z, a1.w};
            float w[4] = {wv.x, wv.y, wv.z, wv.w};
            #pragma unroll
            for (int i = 0; i < 8; i++)
                #pragma unroll
                for (int j = 0; j < 4; j++)
                    acc[i][j] += a[i] * w[j];
        }
        __syncthreads();
    }

    float4 b = *(const float4*)(bias + bn + tx * 4);
    if (gamma_mode) {
        b.x += GAMMA * fmaxf(b.x, 0.f); b.y += GAMMA * fmaxf(b.y, 0.f);
        b.z += GAMMA * fmaxf(b.z, 0.f); b.w += GAMMA * fmaxf(b.w, 0.f);
    }
    #pragma unroll
    for (int i = 0; i < 8; i++) {
        int m = bm + ty * 8 + i;
        float4 o;
        o.x = acc[i][0] + b.x; o.y = acc[i][1] + b.y;
        o.z = acc[i][2] + b.z; o.w = acc[i][3] + b.w;
        if (res) {
            float4 r = *(const float4*)(res + (size_t)m * HID + bn + tx * 4);
            o.x += r.x; o.y += r.y; o.z += r.z; o.w += r.w;
        }
        *(float4*)(C + (size_t)m * HID + bn + tx * 4) = o;
    }
}

// ============ scores = Q @ K^T per (b,h): 128x128 tile, 8x8/thread ============
__global__ __launch_bounds__(256, 2)
void scores_kernel(float* __restrict__ probs)
{
    __shared__ float Qs[32][132];   // [k][m]
    __shared__ float Ks[32][132];   // [k][n]
    const int bh = blockIdx.z;
    const int b = bh / NHEAD, h = bh % NHEAD;
    const int s0 = blockIdx.x * 128;
    const int t0 = blockIdx.y * 128;
    const float* qbase = g_q + (size_t)(b * SEQ + s0) * HID + h * HDIM;
    const float* kbase = g_k + (size_t)(b * SEQ + t0) * HID + h * HDIM;
    const int tid = threadIdx.x;
    const int tx = tid & 15, ty = tid >> 4;
    float acc[8][8] = {};

    #pragma unroll
    for (int k0 = 0; k0 < HDIM; k0 += 32) {
        #pragma unroll
        for (int i = 0; i < 4; i++) {
            int f4 = tid + i * 256;
            int m = f4 >> 3, kk = (f4 & 7) * 4;
            float4 qv = *(const float4*)(qbase + (size_t)m * HID + k0 + kk);
            Qs[kk + 0][m] = qv.x; Qs[kk + 1][m] = qv.y;
            Qs[kk + 2][m] = qv.z; Qs[kk + 3][m] = qv.w;
            float4 kv = *(const float4*)(kbase + (size_t)m * HID + k0 + kk);
            Ks[kk + 0][m] = kv.x; Ks[kk + 1][m] = kv.y;
            Ks[kk + 2][m] = kv.z; Ks[kk + 3][m] = kv.w;
        }
        __syncthreads();
        #pragma unroll
        for (int k = 0; k < 32; k++) {
            float4 q0 = *(const float4*)&Qs[k][ty * 8];
            float4 q1 = *(const float4*)&Qs[k][ty * 8 + 4];
            float4 c0 = *(const float4*)&Ks[k][tx * 8];
            float4 c1 = *(const float4*)&Ks[k][tx * 8 + 4];
            float a[8] = {q0.x, q0.y, q0.z, q0.w, q1.x, q1.y, q1.z, q1.w};
            float bb[8] = {c0.x, c0.y, c0.z, c0.w, c1.x, c1.y, c1.z, c1.w};
            #pragma unroll
            for (int i = 0; i < 8; i++)
                #pragma unroll
                for (int j = 0; j < 8; j++)
                    acc[i][j] += a[i] * bb[j];
        }
        __syncthreads();
    }

    float* out = probs + ((size_t)bh * SEQ + s0) * SEQ + t0;
    #pragma unroll
    for (int i = 0; i < 8; i++) {
        float4 o0 = {acc[i][0], acc[i][1], acc[i][2], acc[i][3]};
        float4 o1 = {acc[i][4], acc[i][5], acc[i][6], acc[i][7]};
        *(float4*)(out + (size_t)(ty * 8 + i) * SEQ + tx * 8) = o0;
        *(float4*)(out + (size_t)(ty * 8 + i) * SEQ + tx * 8 + 4) = o1;
    }
}

// ============ in-place row softmax over 2048 cols (vectorized) ============
__global__ __launch_bounds__(256)
void softmax_kernel(float* __restrict__ probs)
{
    float* p = probs + (size_t)blockIdx.x * SEQ;
    const int tid = threadIdx.x;
    __shared__ float sh[8];

    float4 v[2];
    v[0] = *(const float4*)(p + tid * 4);
    v[1] = *(const float4*)(p + tid * 4 + 1024);
    float mx = fmaxf(fmaxf(fmaxf(v[0].x, v[0].y), fmaxf(v[0].z, v[0].w)),
                     fmaxf(fmaxf(v[1].x, v[1].y), fmaxf(v[1].z, v[1].w)));
    #pragma unroll
    for (int o = 16; o; o >>= 1) mx = fmaxf(mx, __shfl_xor_sync(0xffffffffu, mx, o));
    if ((tid & 31) == 0) sh[tid >> 5] = mx;
    __syncthreads();
    mx = sh[0];
    #pragma unroll
    for (int i = 1; i < 8; i++) mx = fmaxf(mx, sh[i]);
    __syncthreads();

    float sum = 0.f;
    #pragma unroll
    for (int i = 0; i < 2; i++) {
        v[i].x = __expf(v[i].x - mx); v[i].y = __expf(v[i].y - mx);
        v[i].z = __expf(v[i].z - mx); v[i].w = __expf(v[i].w - mx);
        sum += (v[i].x + v[i].y) + (v[i].z + v[i].w);
    }
    #pragma unroll
    for (int o = 16; o; o >>= 1) sum += __shfl_xor_sync(0xffffffffu, sum, o);
    if ((tid & 31) == 0) sh[tid >> 5] = sum;
    __syncthreads();
    sum = 0.f;
    #pragma unroll
    for (int i = 0; i < 8; i++) sum += sh[i];
    float inv = 1.f / sum;
    #pragma unroll
    for (int i = 0; i < 2; i++) {
        v[i].x *= inv; v[i].y *= inv; v[i].z *= inv; v[i].w *= inv;
    }
    *(float4*)(p + tid * 4) = v[0];
    *(float4*)(p + tid * 4 + 1024) = v[1];
}

// ============ ctx = P @ V per (b,h): 128x64 tile, 8x4/thread ============
__global__ __launch_bounds__(256, 2)
void pv_kernel(const float* __restrict__ probs)
{
    __shared__ float Ps[32][132];   // [t][s]
    __shared__ float Vs[32][68];    // [t][d]
    const int bh = blockIdx.y;
    const int b = bh / NHEAD, h = bh % NHEAD;
    const int s0 = blockIdx.x * 128;
    const float* pbase = probs + ((size_t)bh * SEQ + s0) * SEQ;
    const float* vbase = g_v + (size_t)b * SEQ * HID + h * HDIM;
    float* cbase = g_ctx + (size_t)(b * SEQ + s0) * HID + h * HDIM;
    const int tid = threadIdx.x;
    const int tx = tid & 15, ty = tid >> 4;
    float acc[8][4] = {};

    for (int t0 = 0; t0 < SEQ; t0 += 32) {
        // P tile: 128 rows x 32 t = 1024 f4 -> 4/thread
        #pragma unroll
        for (int i = 0; i < 4; i++) {
            int f4 = tid + i * 256;
            int m = f4 >> 3, tt = (f4 & 7) * 4;
            float4 pv = *(const float4*)(pbase + (size_t)m * SEQ + t0 + tt);
            Ps[tt + 0][m] = pv.x; Ps[tt + 1][m] = pv.y;
            Ps[tt + 2][m] = pv.z; Ps[tt + 3][m] = pv.w;
        }
        // V tile: 32 t x 64 d = 512 f4 -> 2/thread (direct f4 store)
        #pragma unroll
        for (int i = 0; i < 2; i++) {
            int f4 = tid + i * 256;
            int t = f4 >> 4, d4 = (f4 & 15) * 4;
            float4 vv = *(const float4*)(vbase + (size_t)(t0 + t) * HID + d4);
            *(float4*)&Vs[t][d4] = vv;
        }
        __syncthreads();
        #pragma unroll
        for (int t = 0; t < 32; t++) {
            float4 p0 = *(const float4*)&Ps[t][ty * 8];
            float4 p1 = *(const float4*)&Ps[t][ty * 8 + 4];
            float4 vv = *(const float4*)&Vs[t][tx * 4];
            float a[8] = {p0.x, p0.y, p0.z, p0.w, p1.x, p1.y, p1.z, p1.w};
            float w[4] = {vv.x, vv.y, vv.z, vv.w};
            #pragma unroll
            for (int i = 0; i < 8; i++)
                #pragma unroll
                for (int j = 0; j < 4; j++)
                    acc[i][j] += a[i] * w[j];
        }
        __syncthreads();
    }

    #pragma unroll
    for (int i = 0; i < 8; i++) {
        float4 o = {acc[i][0], acc[i][1], acc[i][2], acc[i][3]};
        *(float4*)(cbase + (size_t)(ty * 8 + i) * HID + tx * 4) = o;
    }
}

// ============ 'nowb' LayerNorm: (y - mean) / (std_ddof1 + eps) ============
__global__ __launch_bounds__(256)
void ln_kernel(const float* __restrict__ y, float* __restrict__ out)
{
    const float* yr = y + (size_t)blockIdx.x * HID;
    float* orow = out + (size_t)blockIdx.x * HID;
    const int tid = threadIdx.x;
    __shared__ float sh[8];

    float v[3];
    float sum = 0.f;
    #pragma unroll
    for (int i = 0; i < 3; i++) { v[i] = yr[tid + i * 256]; sum += v[i]; }
    #pragma unroll
    for (int o = 16; o; o >>= 1) sum += __shfl_xor_sync(0xffffffffu, sum, o);
    if ((tid & 31) == 0) sh[tid >> 5] = sum;
    __syncthreads();
    sum = 0.f;
    #pragma unroll
    for (int i = 0; i < 8; i++) sum += sh[i];
    float mean = sum * (1.f / HID);
    __syncthreads();

    float ss = 0.f;
    #pragma unroll
    for (int i = 0; i < 3; i++) { float d = v[i] - mean; ss += d * d; }
    #pragma unroll
    for (int o = 16; o; o >>= 1) ss += __shfl_xor_sync(0xffffffffu, ss, o);
    if ((tid & 31) == 0) sh[tid >> 5] = ss;
    __syncthreads();
    ss = 0.f;
    #pragma unroll
    for (int i = 0; i < 8; i++) ss += sh[i];
    float stdv = sqrtf(ss * (1.f / (HID - 1)));   // ddof=1
    float inv = 1.f / (stdv + LNEPS);
    #pragma unroll
    for (int i = 0; i < 3; i++) orow[tid + i * 256] = (v[i] - mean) * inv;
}

// ---------------- launch ----------------
extern "C" void kernel_launch(void* const* d_in, const int* in_sizes, int n_in,
                              void* d_out, int out_size)
{
    const float* x  = (const float*)d_in[0];
    const float* Wq = (const float*)d_in[1];
    const float* bq = (const float*)d_in[2];
    const float* Wk = (const float*)d_in[3];
    const float* bk = (const float*)d_in[4];
    const float* Wv = (const float*)d_in[5];
    const float* bv = (const float*)d_in[6];
    const float* Wo = (const float*)d_in[7];
    const float* bo = (const float*)d_in[8];

    float* out   = (float*)d_out;                       // [B,S,H]
    float* probs = out + (size_t)MTOK * HID;            // [B,NH,S,S]

    float *q, *k, *v, *ctx, *y;
    cudaGetSymbolAddress((void**)&q,   g_q);
    cudaGetSymbolAddress((void**)&k,   g_k);
    cudaGetSymbolAddress((void**)&v,   g_v);
    cudaGetSymbolAddress((void**)&ctx, g_ctx);
    cudaGetSymbolAddress((void**)&y,   g_y);

    dim3 gproj(MTOK / 128, HID / 64);                   // (32, 12)
    proj_gemm<<<gproj, 256>>>(x, Wq, bq, nullptr, q, 0);
    proj_gemm<<<gproj, 256>>>(x, Wk, bk, nullptr, k, 0);
    proj_gemm<<<gproj, 256>>>(x, Wv, bv, nullptr, v, 0);

    scores_kernel<<<dim3(SEQ / 128, SEQ / 128, BATCH * NHEAD), 256>>>(probs);

    softmax_kernel<<<BATCH * NHEAD * SEQ, 256>>>(probs);

    pv_kernel<<<dim3(SEQ / 128, BATCH * NHEAD), 256>>>(probs);

    proj_gemm<<<gproj, 256>>>(ctx, Wo, bo, x, y, 1);    // gamma-modified + residual

    ln_kernel<<<MTOK, 256>>>(y, out);
}

// round 3
// speedup vs baseline: 1.4571x; 1.0674x over previous
#include <cuda_runtime.h>

#define BATCH 2
#define SEQ   2048
#define HID   768
#define NHEAD 12
#define HDIM  64
#define MTOK  (BATCH*SEQ)          // 4096
#define GAMMA 0.05f
#define LNEPS 1e-12f

typedef unsigned long long u64;

// packed f32x2 helpers (Blackwell-only FFMA2 path; identical IEEE rounding to 2x fmaf)
__device__ __forceinline__ void fma2(u64& d, u64 a, u64 b) {
    asm("fma.rn.f32x2 %0, %1, %2, %0;" : "+l"(d) : "l"(a), "l"(b));
}
__device__ __forceinline__ u64 dup2(float x) {
    u64 r; asm("mov.b64 %0, {%1, %1};" : "=l"(r) : "f"(x)); return r;
}
__device__ __forceinline__ float2 unpk2(u64 v) {
    float2 r; asm("mov.b64 {%0, %1}, %2;" : "=f"(r.x), "=f"(r.y) : "l"(v)); return r;
}

// ---------------- scratch (no allocations allowed) ----------------
__device__ float g_q[MTOK*HID];
__device__ float g_k[MTOK*HID];
__device__ float g_v[MTOK*HID];
__device__ float g_ctx[MTOK*HID];
__device__ float g_y[MTOK*HID];

// ============ projection GEMM: C = A @ W^T + bias (+res), 128x64 tile ============
__global__ __launch_bounds__(256, 2)
void proj_gemm(const float* __restrict__ A, const float* __restrict__ W,
               const float* __restrict__ bias, const float* __restrict__ res,
               float* __restrict__ C, int gamma_mode)
{
    __shared__ float As[32][132];   // [k][m]
    __shared__ float Ws[32][68];    // [k][n]
    const int tid = threadIdx.x;
    const int tx = tid & 15, ty = tid >> 4;
    const int bm = blockIdx.x * 128;
    const int bn = blockIdx.y * 64;
    u64 acc2[8][2] = {};

    const float* Abase = A + (size_t)bm * HID;
    const float* Wbase = W + (size_t)bn * HID;

    for (int k0 = 0; k0 < HID; k0 += 32) {
        #pragma unroll
        for (int i = 0; i < 4; i++) {
            int f4 = tid + i * 256;
            int m = f4 >> 3, kk = (f4 & 7) * 4;
            float4 v = *(const float4*)(Abase + (size_t)m * HID + k0 + kk);
            As[kk + 0][m] = v.x; As[kk + 1][m] = v.y;
            As[kk + 2][m] = v.z; As[kk + 3][m] = v.w;
        }
        #pragma unroll
        for (int i = 0; i < 2; i++) {
            int f4 = tid + i * 256;
            int n = f4 >> 3, kk = (f4 & 7) * 4;
            float4 v = *(const float4*)(Wbase + (size_t)n * HID + k0 + kk);
            if (gamma_mode) {
                v.x += GAMMA * fmaxf(v.x, 0.f); v.y += GAMMA * fmaxf(v.y, 0.f);
                v.z += GAMMA * fmaxf(v.z, 0.f); v.w += GAMMA * fmaxf(v.w, 0.f);
            }
            Ws[kk + 0][n] = v.x; Ws[kk + 1][n] = v.y;
            Ws[kk + 2][n] = v.z; Ws[kk + 3][n] = v.w;
        }
        __syncthreads();
        #pragma unroll
        for (int k = 0; k < 32; k++) {
            float4 a0 = *(const float4*)&As[k][ty * 8];
            float4 a1 = *(const float4*)&As[k][ty * 8 + 4];
            ulonglong2 wp = *(const ulonglong2*)&Ws[k][tx * 4];   // 2 packed pairs
            float a[8] = {a0.x, a0.y, a0.z, a0.w, a1.x, a1.y, a1.z, a1.w};
            #pragma unroll
            for (int i = 0; i < 8; i++) {
                u64 ad = dup2(a[i]);
                fma2(acc2[i][0], ad, wp.x);
                fma2(acc2[i][1], ad, wp.y);
            }
        }
        __syncthreads();
    }

    float4 b = *(const float4*)(bias + bn + tx * 4);
    if (gamma_mode) {
        b.x += GAMMA * fmaxf(b.x, 0.f); b.y += GAMMA * fmaxf(b.y, 0.f);
        b.z += GAMMA * fmaxf(b.z, 0.f); b.w += GAMMA * fmaxf(b.w, 0.f);
    }
    #pragma unroll
    for (int i = 0; i < 8; i++) {
        int m = bm + ty * 8 + i;
        float2 c0 = unpk2(acc2[i][0]), c1 = unpk2(acc2[i][1]);
        float4 o;
        o.x = c0.x + b.x; o.y = c0.y + b.y;
        o.z = c1.x + b.z; o.w = c1.y + b.w;
        if (res) {
            float4 r = *(const float4*)(res + (size_t)m * HID + bn + tx * 4);
            o.x += r.x; o.y += r.y; o.z += r.z; o.w += r.w;
        }
        *(float4*)(C + (size_t)m * HID + bn + tx * 4) = o;
    }
}

// ============ scores = Q @ K^T per (b,h): 128x128 tile, 8x8/thread ============
__global__ __launch_bounds__(256, 2)
void scores_kernel(float* __restrict__ probs)
{
    __shared__ float Qs[32][132];   // [k][m]
    __shared__ float Ks[32][132];   // [k][n]
    const int bh = blockIdx.z;
    const int b = bh / NHEAD, h = bh % NHEAD;
    const int s0 = blockIdx.x * 128;
    const int t0 = blockIdx.y * 128;
    const float* qbase = g_q + (size_t)(b * SEQ + s0) * HID + h * HDIM;
    const float* kbase = g_k + (size_t)(b * SEQ + t0) * HID + h * HDIM;
    const int tid = threadIdx.x;
    const int tx = tid & 15, ty = tid >> 4;
    u64 acc2[8][4] = {};

    #pragma unroll
    for (int k0 = 0; k0 < HDIM; k0 += 32) {
        #pragma unroll
        for (int i = 0; i < 4; i++) {
            int f4 = tid + i * 256;
            int m = f4 >> 3, kk = (f4 & 7) * 4;
            float4 qv = *(const float4*)(qbase + (size_t)m * HID + k0 + kk);
            Qs[kk + 0][m] = qv.x; Qs[kk + 1][m] = qv.y;
            Qs[kk + 2][m] = qv.z; Qs[kk + 3][m] = qv.w;
            float4 kv = *(const float4*)(kbase + (size_t)m * HID + k0 + kk);
            Ks[kk + 0][m] = kv.x; Ks[kk + 1][m] = kv.y;
            Ks[kk + 2][m] = kv.z; Ks[kk + 3][m] = kv.w;
        }
        __syncthreads();
        #pragma unroll
        for (int k = 0; k < 32; k++) {
            float4 q0 = *(const float4*)&Qs[k][ty * 8];
            float4 q1 = *(const float4*)&Qs[k][ty * 8 + 4];
            ulonglong2 b01 = *(const ulonglong2*)&Ks[k][tx * 8];      // pairs 0-1
            ulonglong2 b23 = *(const ulonglong2*)&Ks[k][tx * 8 + 4];  // pairs 2-3
            float a[8] = {q0.x, q0.y, q0.z, q0.w, q1.x, q1.y, q1.z, q1.w};
            #pragma unroll
            for (int i = 0; i < 8; i++) {
                u64 ad = dup2(a[i]);
                fma2(acc2[i][0], ad, b01.x);
                fma2(acc2[i][1], ad, b01.y);
                fma2(acc2[i][2], ad, b23.x);
                fma2(acc2[i][3], ad, b23.y);
            }
        }
        __syncthreads();
    }

    float* out = probs + ((size_t)bh * SEQ + s0) * SEQ + t0;
    #pragma unroll
    for (int i = 0; i < 8; i++) {
        float2 c0 = unpk2(acc2[i][0]), c1 = unpk2(acc2[i][1]);
        float2 c2 = unpk2(acc2[i][2]), c3 = unpk2(acc2[i][3]);
        float4 o0 = {c0.x, c0.y, c1.x, c1.y};
        float4 o1 = {c2.x, c2.y, c3.x, c3.y};
        *(float4*)(out + (size_t)(ty * 8 + i) * SEQ + tx * 8) = o0;
        *(float4*)(out + (size_t)(ty * 8 + i) * SEQ + tx * 8 + 4) = o1;
    }
}

// ============ in-place row softmax over 2048 cols (vectorized) ============
__global__ __launch_bounds__(256)
void softmax_kernel(float* __restrict__ probs)
{
    float* p = probs + (size_t)blockIdx.x * SEQ;
    const int tid = threadIdx.x;
    __shared__ float sh[8];

    float4 v[2];
    v[0] = *(const float4*)(p + tid * 4);
    v[1] = *(const float4*)(p + tid * 4 + 1024);
    float mx = fmaxf(fmaxf(fmaxf(v[0].x, v[0].y), fmaxf(v[0].z, v[0].w)),
                     fmaxf(fmaxf(v[1].x, v[1].y), fmaxf(v[1].z, v[1].w)));
    #pragma unroll
    for (int o = 16; o; o >>= 1) mx = fmaxf(mx, __shfl_xor_sync(0xffffffffu, mx, o));
    if ((tid & 31) == 0) sh[tid >> 5] = mx;
    __syncthreads();
    mx = sh[0];
    #pragma unroll
    for (int i = 1; i < 8; i++) mx = fmaxf(mx, sh[i]);
    __syncthreads();

    float sum = 0.f;
    #pragma unroll
    for (int i = 0; i < 2; i++) {
        v[i].x = __expf(v[i].x - mx); v[i].y = __expf(v[i].y - mx);
        v[i].z = __expf(v[i].z - mx); v[i].w = __expf(v[i].w - mx);
        sum += (v[i].x + v[i].y) + (v[i].z + v[i].w);
    }
    #pragma unroll
    for (int o = 16; o; o >>= 1) sum += __shfl_xor_sync(0xffffffffu, sum, o);
    if ((tid & 31) == 0) sh[tid >> 5] = sum;
    __syncthreads();
    sum = 0.f;
    #pragma unroll
    for (int i = 0; i < 8; i++) sum += sh[i];
    float inv = 1.f / sum;
    #pragma unroll
    for (int i = 0; i < 2; i++) {
        v[i].x *= inv; v[i].y *= inv; v[i].z *= inv; v[i].w *= inv;
    }
    *(float4*)(p + tid * 4) = v[0];
    *(float4*)(p + tid * 4 + 1024) = v[1];
}

// ============ ctx = P @ V per (b,h): 128x64 tile, 8x4/thread ============
__global__ __launch_bounds__(256, 2)
void pv_kernel(const float* __restrict__ probs)
{
    __shared__ float Ps[32][132];   // [t][s]
    __shared__ float Vs[32][68];    // [t][d]
    const int bh = blockIdx.y;
    const int b = bh / NHEAD, h = bh % NHEAD;
    const int s0 = blockIdx.x * 128;
    const float* pbase = probs + ((size_t)bh * SEQ + s0) * SEQ;
    const float* vbase = g_v + (size_t)b * SEQ * HID + h * HDIM;
    float* cbase = g_ctx + (size_t)(b * SEQ + s0) * HID + h * HDIM;
    const int tid = threadIdx.x;
    const int tx = tid & 15, ty = tid >> 4;
    u64 acc2[8][2] = {};

    for (int t0 = 0; t0 < SEQ; t0 += 32) {
        #pragma unroll
        for (int i = 0; i < 4; i++) {
            int f4 = tid + i * 256;
            int m = f4 >> 3, tt = (f4 & 7) * 4;
            float4 pv = *(const float4*)(pbase + (size_t)m * SEQ + t0 + tt);
            Ps[tt + 0][m] = pv.x; Ps[tt + 1][m] = pv.y;
            Ps[tt + 2][m] = pv.z; Ps[tt + 3][m] = pv.w;
        }
        #pragma unroll
        for (int i = 0; i < 2; i++) {
            int f4 = tid + i * 256;
            int t = f4 >> 4, d4 = (f4 & 15) * 4;
            float4 vv = *(const float4*)(vbase + (size_t)(t0 + t) * HID + d4);
            *(float4*)&Vs[t][d4] = vv;
        }
        __syncthreads();
        #pragma unroll
        for (int t = 0; t < 32; t++) {
            float4 p0 = *(const float4*)&Ps[t][ty * 8];
            float4 p1 = *(const float4*)&Ps[t][ty * 8 + 4];
            ulonglong2 vp = *(const ulonglong2*)&Vs[t][tx * 4];
            float a[8] = {p0.x, p0.y, p0.z, p0.w, p1.x, p1.y, p1.z, p1.w};
            #pragma unroll
            for (int i = 0; i < 8; i++) {
                u64 ad = dup2(a[i]);
                fma2(acc2[i][0], ad, vp.x);
                fma2(acc2[i][1], ad, vp.y);
            }
        }
        __syncthreads();
    }

    #pragma unroll
    for (int i = 0; i < 8; i++) {
        float2 c0 = unpk2(acc2[i][0]), c1 = unpk2(acc2[i][1]);
        float4 o = {c0.x, c0.y, c1.x, c1.y};
        *(float4*)(cbase + (size_t)(ty * 8 + i) * HID + tx * 4) = o;
    }
}

// ============ 'nowb' LayerNorm: (y - mean) / (std_ddof1 + eps) ============
__global__ __launch_bounds__(256)
void ln_kernel(const float* __restrict__ y, float* __restrict__ out)
{
    const float* yr = y + (size_t)blockIdx.x * HID;
    float* orow = out + (size_t)blockIdx.x * HID;
    const int tid = threadIdx.x;
    __shared__ float sh[8];

    float v[3];
    float sum = 0.f;
    #pragma unroll
    for (int i = 0; i < 3; i++) { v[i] = yr[tid + i * 256]; sum += v[i]; }
    #pragma unroll
    for (int o = 16; o; o >>= 1) sum += __shfl_xor_sync(0xffffffffu, sum, o);
    if ((tid & 31) == 0) sh[tid >> 5] = sum;
    __syncthreads();
    sum = 0.f;
    #pragma unroll
    for (int i = 0; i < 8; i++) sum += sh[i];
    float mean = sum * (1.f / HID);
    __syncthreads();

    float ss = 0.f;
    #pragma unroll
    for (int i = 0; i < 3; i++) { float d = v[i] - mean; ss += d * d; }
    #pragma unroll
    for (int o = 16; o; o >>= 1) ss += __shfl_xor_sync(0xffffffffu, ss, o);
    if ((tid & 31) == 0) sh[tid >> 5] = ss;
    __syncthreads();
    ss = 0.f;
    #pragma unroll
    for (int i = 0; i < 8; i++) ss += sh[i];
    float stdv = sqrtf(ss * (1.f / (HID - 1)));   // ddof=1
    float inv = 1.f / (stdv + LNEPS);
    #pragma unroll
    for (int i = 0; i < 3; i++) orow[tid + i * 256] = (v[i] - mean) * inv;
}

// ---------------- launch ----------------
extern "C" void kernel_launch(void* const* d_in, const int* in_sizes, int n_in,
                              void* d_out, int out_size)
{
    const float* x  = (const float*)d_in[0];
    const float* Wq = (const float*)d_in[1];
    const float* bq = (const float*)d_in[2];
    const float* Wk = (const float*)d_in[3];
    const float* bk = (const float*)d_in[4];
    const float* Wv = (const float*)d_in[5];
    const float* bv = (const float*)d_in[6];
    const float* Wo = (const float*)d_in[7];
    const float* bo = (const float*)d_in[8];

    float* out   = (float*)d_out;                       // [B,S,H]
    float* probs = out + (size_t)MTOK * HID;            // [B,NH,S,S]

    float *q, *k, *v, *ctx, *y;
    cudaGetSymbolAddress((void**)&q,   g_q);
    cudaGetSymbolAddress((void**)&k,   g_k);
    cudaGetSymbolAddress((void**)&v,   g_v);
    cudaGetSymbolAddress((void**)&ctx, g_ctx);
    cudaGetSymbolAddress((void**)&y,   g_y);

    dim3 gproj(MTOK / 128, HID / 64);                   // (32, 12)
    proj_gemm<<<gproj, 256>>>(x, Wq, bq, nullptr, q, 0);
    proj_gemm<<<gproj, 256>>>(x, Wk, bk, nullptr, k, 0);
    proj_gemm<<<gproj, 256>>>(x, Wv, bv, nullptr, v, 0);

    scores_kernel<<<dim3(SEQ / 128, SEQ / 128, BATCH * NHEAD), 256>>>(probs);

    softmax_kernel<<<BATCH * NHEAD * SEQ, 256>>>(probs);

    pv_kernel<<<dim3(SEQ / 128, BATCH * NHEAD), 256>>>(probs);

    proj_gemm<<<gproj, 256>>>(ctx, Wo, bo, x, y, 1);    // gamma-modified + residual

    ln_kernel<<<MTOK, 256>>>(y, out);
}

// round 5
// speedup vs baseline: 1.9432x; 1.3335x over previous
#include <cuda_runtime.h>
#include <cuda_bf16.h>
#include <mma.h>
#include <cstdint>

using namespace nvcuda;

#define BATCH 2
#define SEQ   2048
#define HID   768
#define NHEAD 12
#define HDIM  64
#define MTOK  (BATCH*SEQ)
#define GAMMA 0.05f
#define LNEPS 1e-12f
#define SPAD  88      // smem row pitch in bf16 elems: 176B, 16B-aligned, bank-staggered

typedef unsigned long long u64;

// ---------- packed f32x2 helpers ----------
__device__ __forceinline__ void fma2(u64& d, u64 a, u64 b) {
    asm("fma.rn.f32x2 %0, %1, %2, %0;" : "+l"(d) : "l"(a), "l"(b));
}
__device__ __forceinline__ u64 dup2(float x) {
    u64 r; asm("mov.b64 %0, {%1, %1};" : "=l"(r) : "f"(x)); return r;
}
__device__ __forceinline__ float2 unpk2(u64 v) {
    float2 r; asm("mov.b64 {%0, %1}, %2;" : "=f"(r.x), "=f"(r.y) : "l"(v)); return r;
}

// ---------------- scratch ----------------
__device__ __nv_bfloat16 g_qhi[MTOK*HID];
__device__ __nv_bfloat16 g_qlo[MTOK*HID];
__device__ __nv_bfloat16 g_khi[MTOK*HID];
__device__ __nv_bfloat16 g_klo[MTOK*HID];
__device__ __nv_bfloat16 g_vb [MTOK*HID];
__device__ __nv_bfloat16 g_pbf[(size_t)BATCH*NHEAD*SEQ*SEQ];
__device__ float g_ctx[MTOK*HID];
__device__ float g_y[MTOK*HID];

// ============ projection GEMM: C = A @ W^T + bias (+res) ============
// optional outputs: fp32 C, bf16 hi/lo split, single bf16
__global__ __launch_bounds__(256, 2)
void proj_gemm(const float* __restrict__ A, const float* __restrict__ W,
               const float* __restrict__ bias, const float* __restrict__ res,
               float* __restrict__ C,
               __nv_bfloat16* __restrict__ hi, __nv_bfloat16* __restrict__ lo,
               __nv_bfloat16* __restrict__ bs,
               int gamma_mode)
{
    __shared__ float As[32][132];
    __shared__ float Ws[32][68];
    const int tid = threadIdx.x;
    const int tx = tid & 15, ty = tid >> 4;
    const int bm = blockIdx.x * 128;
    const int bn = blockIdx.y * 64;
    u64 acc2[8][2] = {};

    const float* Abase = A + (size_t)bm * HID;
    const float* Wbase = W + (size_t)bn * HID;

    for (int k0 = 0; k0 < HID; k0 += 32) {
        #pragma unroll
        for (int i = 0; i < 4; i++) {
            int f4 = tid + i * 256;
            int m = f4 >> 3, kk = (f4 & 7) * 4;
            float4 v = *(const float4*)(Abase + (size_t)m * HID + k0 + kk);
            As[kk + 0][m] = v.x; As[kk + 1][m] = v.y;
            As[kk + 2][m] = v.z; As[kk + 3][m] = v.w;
        }
        #pragma unroll
        for (int i = 0; i < 2; i++) {
            int f4 = tid + i * 256;
            int n = f4 >> 3, kk = (f4 & 7) * 4;
            float4 v = *(const float4*)(Wbase + (size_t)n * HID + k0 + kk);
            if (gamma_mode) {
                v.x += GAMMA * fmaxf(v.x, 0.f); v.y += GAMMA * fmaxf(v.y, 0.f);
                v.z += GAMMA * fmaxf(v.z, 0.f); v.w += GAMMA * fmaxf(v.w, 0.f);
            }
            Ws[kk + 0][n] = v.x; Ws[kk + 1][n] = v.y;
            Ws[kk + 2][n] = v.z; Ws[kk + 3][n] = v.w;
        }
        __syncthreads();
        #pragma unroll
        for (int k = 0; k < 32; k++) {
            float4 a0 = *(const float4*)&As[k][ty * 8];
            float4 a1 = *(const float4*)&As[k][ty * 8 + 4];
            ulonglong2 wp = *(const ulonglong2*)&Ws[k][tx * 4];
            float a[8] = {a0.x, a0.y, a0.z, a0.w, a1.x, a1.y, a1.z, a1.w};
            #pragma unroll
            for (int i = 0; i < 8; i++) {
                u64 ad = dup2(a[i]);
                fma2(acc2[i][0], ad, wp.x);
                fma2(acc2[i][1], ad, wp.y);
            }
        }
        __syncthreads();
    }

    float4 b = *(const float4*)(bias + bn + tx * 4);
    if (gamma_mode) {
        b.x += GAMMA * fmaxf(b.x, 0.f); b.y += GAMMA * fmaxf(b.y, 0.f);
        b.z += GAMMA * fmaxf(b.z, 0.f); b.w += GAMMA * fmaxf(b.w, 0.f);
    }
    #pragma unroll
    for (int i = 0; i < 8; i++) {
        int m = bm + ty * 8 + i;
        size_t base = (size_t)m * HID + bn + tx * 4;
        float2 c0 = unpk2(acc2[i][0]), c1 = unpk2(acc2[i][1]);
        float4 o;
        o.x = c0.x + b.x; o.y = c0.y + b.y;
        o.z = c1.x + b.z; o.w = c1.y + b.w;
        if (res) {
            float4 r = *(const float4*)(res + base);
            o.x += r.x; o.y += r.y; o.z += r.z; o.w += r.w;
        }
        if (C) *(float4*)(C + base) = o;
        if (hi) {
            __nv_bfloat16 h0 = __float2bfloat16(o.x), h1 = __float2bfloat16(o.y);
            __nv_bfloat16 h2 = __float2bfloat16(o.z), h3 = __float2bfloat16(o.w);
            __nv_bfloat16 l0 = __float2bfloat16(o.x - __bfloat162float(h0));
            __nv_bfloat16 l1 = __float2bfloat16(o.y - __bfloat162float(h1));
            __nv_bfloat16 l2 = __float2bfloat16(o.z - __bfloat162float(h2));
            __nv_bfloat16 l3 = __float2bfloat16(o.w - __bfloat162float(h3));
            __nv_bfloat162 hp0 = __halves2bfloat162(h0, h1), hp1 = __halves2bfloat162(h2, h3);
            __nv_bfloat162 lp0 = __halves2bfloat162(l0, l1), lp1 = __halves2bfloat162(l2, l3);
            uint2 hu, lu;
            hu.x = *(uint32_t*)&hp0; hu.y = *(uint32_t*)&hp1;
            lu.x = *(uint32_t*)&lp0; lu.y = *(uint32_t*)&lp1;
            *(uint2*)(hi + base) = hu;
            *(uint2*)(lo + base) = lu;
        }
        if (bs) {
            __nv_bfloat162 p0 = __floats2bfloat162_rn(o.x, o.y);
            __nv_bfloat162 p1 = __floats2bfloat162_rn(o.z, o.w);
            uint2 u;
            u.x = *(uint32_t*)&p0; u.y = *(uint32_t*)&p1;
            *(uint2*)(bs + base) = u;
        }
    }
}

// ============ scores via WMMA bf16 3-pass: S = Qhi Khi^T + Qhi Klo^T + Qlo Khi^T ============
#define SC_TILE (128 * SPAD)
#define SC_SMEM (4 * SC_TILE * 2)   // bytes = 90112

__device__ __forceinline__ void ld_tile128(__nv_bfloat16* dst, const __nv_bfloat16* src, int tid)
{
    #pragma unroll
    for (int i = 0; i < 4; i++) {
        int idx = tid + i * 256;
        int r = idx >> 3, c8 = (idx & 7) * 8;
        uint4 v = *(const uint4*)(src + (size_t)r * HID + c8);
        *(uint4*)(dst + r * SPAD + c8) = v;
    }
}

__global__ __launch_bounds__(256)
void scores_mma(float* __restrict__ probs)
{
    extern __shared__ __nv_bfloat16 sm[];
    __nv_bfloat16* Qhi = sm;
    __nv_bfloat16* Qlo = sm + SC_TILE;
    __nv_bfloat16* Khi = sm + 2 * SC_TILE;
    __nv_bfloat16* Klo = sm + 3 * SC_TILE;

    const int tid = threadIdx.x, wid = tid >> 5;
    const int bh = blockIdx.z;
    const int b = bh / NHEAD, h = bh % NHEAD;
    const int s0 = blockIdx.x * 128;
    const int t0 = blockIdx.y * 128;

    const size_t qb = (size_t)(b * SEQ + s0) * HID + h * HDIM;
    const size_t kb = (size_t)(b * SEQ + t0) * HID + h * HDIM;
    ld_tile128(Qhi, g_qhi + qb, tid);
    ld_tile128(Qlo, g_qlo + qb, tid);
    ld_tile128(Khi, g_khi + kb, tid);
    ld_tile128(Klo, g_klo + kb, tid);
    __syncthreads();

    const int wm = wid & 3;       // 4 m-warps of 32 rows
    const int wn = wid >> 2;      // 2 n-warps of 64 cols

    wmma::fragment<wmma::accumulator, 16, 16, 16, float> acc[2][4];
    #pragma unroll
    for (int i = 0; i < 2; i++)
        #pragma unroll
        for (int j = 0; j < 4; j++)
            wmma::fill_fragment(acc[i][j], 0.f);

    #pragma unroll
    for (int pass = 0; pass < 3; pass++) {
        const __nv_bfloat16* A = (pass == 2) ? Qlo : Qhi;
        const __nv_bfloat16* B = (pass == 1) ? Klo : Khi;
        #pragma unroll
        for (int k0 = 0; k0 < HDIM; k0 += 16) {
            wmma::fragment<wmma::matrix_a, 16, 16, 16, __nv_bfloat16, wmma::row_major> af[2];
            wmma::fragment<wmma::matrix_b, 16, 16, 16, __nv_bfloat16, wmma::col_major> bf[4];
            #pragma unroll
            for (int i = 0; i < 2; i++)
                wmma::load_matrix_sync(af[i], A + (wm * 32 + i * 16) * SPAD + k0, SPAD);
            #pragma unroll
            for (int j = 0; j < 4; j++)
                wmma::load_matrix_sync(bf[j], B + (wn * 64 + j * 16) * SPAD + k0, SPAD);
            #pragma unroll
            for (int i = 0; i < 2; i++)
                #pragma unroll
                for (int j = 0; j < 4; j++)
                    wmma::mma_sync(acc[i][j], af[i], bf[j], acc[i][j]);
        }
    }

    #pragma unroll
    for (int i = 0; i < 2; i++)
        #pragma unroll
        for (int j = 0; j < 4; j++) {
            float* op = probs + ((size_t)bh * SEQ + s0 + wm * 32 + i * 16) * SEQ
                        + t0 + wn * 64 + j * 16;
            wmma::store_matrix_sync(op, acc[i][j], SEQ, wmma::mem_row_major);
        }
}

// ============ softmax: fp32 in-place + bf16 copy for PV ============
__global__ __launch_bounds__(256)
void softmax_kernel(float* __restrict__ probs, __nv_bfloat16* __restrict__ pbf)
{
    float* p = probs + (size_t)blockIdx.x * SEQ;
    __nv_bfloat16* pb = pbf + (size_t)blockIdx.x * SEQ;
    const int tid = threadIdx.x;
    __shared__ float sh[8];

    float4 v[2];
    v[0] = *(const float4*)(p + tid * 8);
    v[1] = *(const float4*)(p + tid * 8 + 4);
    float mx = fmaxf(fmaxf(fmaxf(v[0].x, v[0].y), fmaxf(v[0].z, v[0].w)),
                     fmaxf(fmaxf(v[1].x, v[1].y), fmaxf(v[1].z, v[1].w)));
    #pragma unroll
    for (int o = 16; o; o >>= 1) mx = fmaxf(mx, __shfl_xor_sync(0xffffffffu, mx, o));
    if ((tid & 31) == 0) sh[tid >> 5] = mx;
    __syncthreads();
    mx = sh[0];
    #pragma unroll
    for (int i = 1; i < 8; i++) mx = fmaxf(mx, sh[i]);
    __syncthreads();

    float sum = 0.f;
    #pragma unroll
    for (int i = 0; i < 2; i++) {
        v[i].x = __expf(v[i].x - mx); v[i].y = __expf(v[i].y - mx);
        v[i].z = __expf(v[i].z - mx); v[i].w = __expf(v[i].w - mx);
        sum += (v[i].x + v[i].y) + (v[i].z + v[i].w);
    }
    #pragma unroll
    for (int o = 16; o; o >>= 1) sum += __shfl_xor_sync(0xffffffffu, sum, o);
    if ((tid & 31) == 0) sh[tid >> 5] = sum;
    __syncthreads();
    sum = 0.f;
    #pragma unroll
    for (int i = 0; i < 8; i++) sum += sh[i];
    float inv = 1.f / sum;
    #pragma unroll
    for (int i = 0; i < 2; i++) {
        v[i].x *= inv; v[i].y *= inv; v[i].z *= inv; v[i].w *= inv;
    }
    *(float4*)(p + tid * 8) = v[0];
    *(float4*)(p + tid * 8 + 4) = v[1];

    __nv_bfloat162 b0 = __floats2bfloat162_rn(v[0].x, v[0].y);
    __nv_bfloat162 b1 = __floats2bfloat162_rn(v[0].z, v[0].w);
    __nv_bfloat162 b2 = __floats2bfloat162_rn(v[1].x, v[1].y);
    __nv_bfloat162 b3 = __floats2bfloat162_rn(v[1].z, v[1].w);
    uint4 u;
    u.x = *(uint32_t*)&b0; u.y = *(uint32_t*)&b1;
    u.z = *(uint32_t*)&b2; u.w = *(uint32_t*)&b3;
    *(uint4*)(pb + tid * 8) = u;
}

// ============ ctx = P @ V via WMMA bf16 single pass ============
__global__ __launch_bounds__(256)
void pv_mma()
{
    __shared__ __nv_bfloat16 Pb[128 * SPAD];
    __shared__ __nv_bfloat16 Vb[64 * SPAD];
    const int tid = threadIdx.x, wid = tid >> 5;
    const int bh = blockIdx.y;
    const int b = bh / NHEAD, h = bh % NHEAD;
    const int s0 = blockIdx.x * 128;

    const __nv_bfloat16* pbase = g_pbf + ((size_t)bh * SEQ + s0) * SEQ;
    const __nv_bfloat16* vbase = g_vb + (size_t)b * SEQ * HID + h * HDIM;

    const int wm = wid & 3;     // 4 m-warps x 32 rows
    const int wn = wid >> 2;    // 2 n-warps x 32 cols

    wmma::fragment<wmma::accumulator, 16, 16, 16, float> acc[2][2];
    #pragma unroll
    for (int i = 0; i < 2; i++)
        #pragma unroll
        for (int j = 0; j < 2; j++)
            wmma::fill_fragment(acc[i][j], 0.f);

    for (int t0 = 0; t0 < SEQ; t0 += 64) {
        #pragma unroll
        for (int i = 0; i < 4; i++) {
            int idx = tid + i * 256;
            int r = idx >> 3, c8 = (idx & 7) * 8;
            uint4 v = *(const uint4*)(pbase + (size_t)r * SEQ + t0 + c8);
            *(uint4*)(Pb + r * SPAD + c8) = v;
        }
        #pragma unroll
        for (int i = 0; i < 2; i++) {
            int idx = tid + i * 256;
            int r = idx >> 3, c8 = (idx & 7) * 8;
            uint4 v = *(const uint4*)(vbase + (size_t)(t0 + r) * HID + c8);
            *(uint4*)(Vb + r * SPAD + c8) = v;
        }
        __syncthreads();
        #pragma unroll
        for (int k0 = 0; k0 < 64; k0 += 16) {
            wmma::fragment<wmma::matrix_a, 16, 16, 16, __nv_bfloat16, wmma::row_major> af[2];
            wmma::fragment<wmma::matrix_b, 16, 16, 16, __nv_bfloat16, wmma::row_major> bf[2];
            #pragma unroll
            for (int i = 0; i < 2; i++)
                wmma::load_matrix_sync(af[i], Pb + (wm * 32 + i * 16) * SPAD + k0, SPAD);
            #pragma unroll
            for (int j = 0; j < 2; j++)
                wmma::load_matrix_sync(bf[j], Vb + k0 * SPAD + wn * 32 + j * 16, SPAD);
            #pragma unroll
            for (int i = 0; i < 2; i++)
                #pragma unroll
                for (int j = 0; j < 2; j++)
                    wmma::mma_sync(acc[i][j], af[i], bf[j], acc[i][j]);
        }
        __syncthreads();
    }

    #pragma unroll
    for (int i = 0; i < 2; i++)
        #pragma unroll
        for (int j = 0; j < 2; j++) {
            float* op = g_ctx + (size_t)(b * SEQ + s0 + wm * 32 + i * 16) * HID
                        + h * HDIM + wn * 32 + j * 16;
            wmma::store_matrix_sync(op, acc[i][j], HID, wmma::mem_row_major);
        }
}

// ============ 'nowb' LayerNorm ============
__global__ __launch_bounds__(256)
void ln_kernel(const float* __restrict__ y, float* __restrict__ out)
{
    const float* yr = y + (size_t)blockIdx.x * HID;
    float* orow = out + (size_t)blockIdx.x * HID;
    const int tid = threadIdx.x;
    __shared__ float sh[8];

    float v[3];
    float sum = 0.f;
    #pragma unroll
    for (int i = 0; i < 3; i++) { v[i] = yr[tid + i * 256]; sum += v[i]; }
    #pragma unroll
    for (int o = 16; o; o >>= 1) sum += __shfl_xor_sync(0xffffffffu, sum, o);
    if ((tid & 31) == 0) sh[tid >> 5] = sum;
    __syncthreads();
    sum = 0.f;
    #pragma unroll
    for (int i = 0; i < 8; i++) sum += sh[i];
    float mean = sum * (1.f / HID);
    __syncthreads();

    float ss = 0.f;
    #pragma unroll
    for (int i = 0; i < 3; i++) { float d = v[i] - mean; ss += d * d; }
    #pragma unroll
    for (int o = 16; o; o >>= 1) ss += __shfl_xor_sync(0xffffffffu, ss, o);
    if ((tid & 31) == 0) sh[tid >> 5] = ss;
    __syncthreads();
    ss = 0.f;
    #pragma unroll
    for (int i = 0; i < 8; i++) ss += sh[i];
    float stdv = sqrtf(ss * (1.f / (HID - 1)));
    float inv = 1.f / (stdv + LNEPS);
    #pragma unroll
    for (int i = 0; i < 3; i++) orow[tid + i * 256] = (v[i] - mean) * inv;
}

// ---------------- launch ----------------
extern "C" void kernel_launch(void* const* d_in, const int* in_sizes, int n_in,
                              void* d_out, int out_size)
{
    const float* x  = (const float*)d_in[0];
    const float* Wq = (const float*)d_in[1];
    const float* bq = (const float*)d_in[2];
    const float* Wk = (const float*)d_in[3];
    const float* bk = (const float*)d_in[4];
    const float* Wv = (const float*)d_in[5];
    const float* bv = (const float*)d_in[6];
    const float* Wo = (const float*)d_in[7];
    const float* bo = (const float*)d_in[8];

    float* out   = (float*)d_out;
    float* probs = out + (size_t)MTOK * HID;

    float *ctx, *y;
    __nv_bfloat16 *qhi, *qlo, *khi, *klo, *vb, *pbf;
    cudaGetSymbolAddress((void**)&ctx, g_ctx);
    cudaGetSymbolAddress((void**)&y,   g_y);
    cudaGetSymbolAddress((void**)&qhi, g_qhi);
    cudaGetSymbolAddress((void**)&qlo, g_qlo);
    cudaGetSymbolAddress((void**)&khi, g_khi);
    cudaGetSymbolAddress((void**)&klo, g_klo);
    cudaGetSymbolAddress((void**)&vb,  g_vb);
    cudaGetSymbolAddress((void**)&pbf, g_pbf);

    cudaFuncSetAttribute(scores_mma, cudaFuncAttributeMaxDynamicSharedMemorySize, SC_SMEM);

    dim3 gproj(MTOK / 128, HID / 64);
    proj_gemm<<<gproj, 256>>>(x, Wq, bq, nullptr, nullptr, qhi, qlo, nullptr, 0);
    proj_gemm<<<gproj, 256>>>(x, Wk, bk, nullptr, nullptr, khi, klo, nullptr, 0);
    proj_gemm<<<gproj, 256>>>(x, Wv, bv, nullptr, nullptr, nullptr, nullptr, vb, 0);

    scores_mma<<<dim3(SEQ / 128, SEQ / 128, BATCH * NHEAD), 256, SC_SMEM>>>(probs);

    softmax_kernel<<<BATCH * NHEAD * SEQ, 256>>>(probs, pbf);

    pv_mma<<<dim3(SEQ / 128, BATCH * NHEAD), 256>>>();

    proj_gemm<<<gproj, 256>>>(ctx, Wo, bo, x, y, nullptr, nullptr, nullptr, 1);

    ln_kernel<<<MTOK, 256>>>(y, out);
}